// round 17
// baseline (speedup 1.0000x reference)
#include <cuda_runtime.h>
#include <cuda_bf16.h>
#include <cstdint>

// ---------------- problem constants ----------------
#define T_SEQ   4096
#define D_MODEL 1024
#define NHEADS  16
#define NKV     4
#define HD      64
#define KVD     (NKV*HD)     // 256
#define WINDOW  256

// ---------------- scratch (all bf16 hi/lo pairs) ----------------
__device__ __nv_bfloat16 g_xh[T_SEQ * D_MODEL],  g_xl[T_SEQ * D_MODEL];
__device__ __nv_bfloat16 g_wqt_h[D_MODEL * D_MODEL], g_wqt_l[D_MODEL * D_MODEL]; // W^T [n][k]
__device__ __nv_bfloat16 g_wot_h[D_MODEL * D_MODEL], g_wot_l[D_MODEL * D_MODEL];
__device__ __nv_bfloat16 g_wkt_h[KVD * D_MODEL],     g_wkt_l[KVD * D_MODEL];
__device__ __nv_bfloat16 g_wvt_h[KVD * D_MODEL],     g_wvt_l[KVD * D_MODEL];
__device__ __nv_bfloat16 g_qh[T_SEQ * D_MODEL],  g_ql[T_SEQ * D_MODEL];
__device__ __nv_bfloat16 g_kh[T_SEQ * KVD],      g_kl[T_SEQ * KVD];
__device__ __nv_bfloat16 g_vh[T_SEQ * KVD],      g_vl[T_SEQ * KVD];
__device__ __nv_bfloat16 g_ah[T_SEQ * D_MODEL],  g_al[T_SEQ * D_MODEL];

// ================= helpers =================
__device__ __forceinline__ void mma_bf16(float d[4], const unsigned a[4], const unsigned b[2])
{
    asm volatile(
        "mma.sync.aligned.m16n8k16.row.col.f32.bf16.bf16.f32 "
        "{%0,%1,%2,%3}, {%4,%5,%6,%7}, {%8,%9}, {%0,%1,%2,%3};\n"
        : "+f"(d[0]), "+f"(d[1]), "+f"(d[2]), "+f"(d[3])
        : "r"(a[0]), "r"(a[1]), "r"(a[2]), "r"(a[3]), "r"(b[0]), "r"(b[1]));
}

__device__ __forceinline__ void ldsm_x4(unsigned r[4], unsigned addr)
{
    asm volatile("ldmatrix.sync.aligned.m8n8.x4.shared.b16 {%0,%1,%2,%3}, [%4];"
                 : "=r"(r[0]), "=r"(r[1]), "=r"(r[2]), "=r"(r[3]) : "r"(addr));
}

__device__ __forceinline__ void split2(float a, float b, unsigned& h, unsigned& l)
{
    __nv_bfloat16 ha = __float2bfloat16(a), hb = __float2bfloat16(b);
    __nv_bfloat16 la = __float2bfloat16(a - __bfloat162float(ha));
    __nv_bfloat16 lb = __float2bfloat16(b - __bfloat162float(hb));
    __nv_bfloat162 hh; hh.x = ha; hh.y = hb;
    __nv_bfloat162 ll; ll.x = la; ll.y = lb;
    h = *reinterpret_cast<unsigned*>(&hh);
    l = *reinterpret_cast<unsigned*>(&ll);
}

__device__ __forceinline__ void split8(const float* x, unsigned h[4], unsigned l[4])
{
#pragma unroll
    for (int p = 0; p < 4; p++) split2(x[2 * p], x[2 * p + 1], h[p], l[p]);
}

__device__ __forceinline__ float ex2(float x)
{
    float r;
    asm("ex2.approx.ftz.f32 %0, %1;" : "=f"(r) : "f"(x));
    return r;
}

__device__ __forceinline__ void cp16(uint32_t dst, const void* src)
{
    asm volatile("cp.async.cg.shared.global [%0], [%1], 16;" :: "r"(dst), "l"(src) : "memory");
}
__device__ __forceinline__ void cp_commit()
{
    asm volatile("cp.async.commit_group;" ::: "memory");
}
__device__ __forceinline__ void cp_wait1()
{
    asm volatile("cp.async.wait_group 1;" ::: "memory");
}
__device__ __forceinline__ void cp_wait0()
{
    asm volatile("cp.async.wait_group 0;" ::: "memory");
}

// ================= one-time conversion kernels =================
// x (fp32) -> bf16 hi/lo
__global__ __launch_bounds__(256) void conv_x(const float* __restrict__ x)
{
    const size_t i = ((size_t)blockIdx.x * 256 + threadIdx.x) * 8;
    float f[8];
    float4 v0 = *(const float4*)&x[i];
    float4 v1 = *(const float4*)&x[i + 4];
    f[0]=v0.x; f[1]=v0.y; f[2]=v0.z; f[3]=v0.w;
    f[4]=v1.x; f[5]=v1.y; f[6]=v1.z; f[7]=v1.w;
    unsigned h[4], l[4];
    split8(f, h, l);
    *(uint4*)&g_xh[i] = make_uint4(h[0], h[1], h[2], h[3]);
    *(uint4*)&g_xl[i] = make_uint4(l[0], l[1], l[2], l[3]);
}

// W [k=1024][n] fp32 -> W^T [n][k=1024] bf16 hi/lo. z selects the matrix.
__global__ __launch_bounds__(256) void conv_wt(
    const float* __restrict__ Wq, const float* __restrict__ Wo,
    const float* __restrict__ Wk, const float* __restrict__ Wv)
{
    __shared__ __nv_bfloat16 sh[64][72];
    __shared__ __nv_bfloat16 sl[64][72];

    const int z = blockIdx.z;
    const float* W; __nv_bfloat16 *Th, *Tl; int Nw;
    if      (z == 0) { W = Wq; Th = g_wqt_h; Tl = g_wqt_l; Nw = D_MODEL; }
    else if (z == 1) { W = Wo; Th = g_wot_h; Tl = g_wot_l; Nw = D_MODEL; }
    else if (z == 2) { W = Wk; Th = g_wkt_h; Tl = g_wkt_l; Nw = KVD; }
    else             { W = Wv; Th = g_wvt_h; Tl = g_wvt_l; Nw = KVD; }
    if (blockIdx.x * 64 >= Nw) return;   // uniform per block

    const int n0 = blockIdx.x * 64, k0 = blockIdx.y * 64;
    const int tid = threadIdx.x;
    const int tx = tid & 15, ty = tid >> 4;

#pragma unroll
    for (int i = 0; i < 4; i++) {
        const int k = ty + 16 * i;
        float4 v = *(const float4*)&W[(size_t)(k0 + k) * Nw + n0 + tx * 4];
        float f[4] = { v.x, v.y, v.z, v.w };
#pragma unroll
        for (int e = 0; e < 4; e++) {
            __nv_bfloat16 hh = __float2bfloat16(f[e]);
            __nv_bfloat16 ll = __float2bfloat16(f[e] - __bfloat162float(hh));
            sh[tx * 4 + e][k] = hh;
            sl[tx * 4 + e][k] = ll;
        }
    }
    __syncthreads();

    const int n = tid >> 2, kq = tid & 3;
    const size_t o = (size_t)(n0 + n) * D_MODEL + k0 + kq * 16;
    *(uint4*)&Th[o]     = *(uint4*)&sh[n][kq * 16];
    *(uint4*)&Th[o + 8] = *(uint4*)&sh[n][kq * 16 + 8];
    *(uint4*)&Tl[o]     = *(uint4*)&sl[n][kq * 16];
    *(uint4*)&Tl[o + 8] = *(uint4*)&sl[n][kq * 16 + 8];
}

// ================= bf16-input tensor-core GEMM with cp.async =================
// C(128x128 tile) = A@B^T + bias. A: [m][k] bf16 hi/lo; B: W^T [n][k] bf16 hi/lo.
// 3-product mma (hh + hl + lh), BK=16, double buffered, ldmatrix frags.
#define GBK  16
#define GSTR 24
#define GARR (128 * GSTR * 2)     // 6144 B per array
#define GBUF (4 * GARR)           // 24576 B per buffer (Ah,Al,Bh,Bl)
#define GSM_TOTAL (2 * GBUF)      // 49152 B

template<bool BF16OUT>
__device__ __forceinline__ void gemm_body(
    const __nv_bfloat16* __restrict__ Agh, const __nv_bfloat16* __restrict__ Agl,
    const __nv_bfloat16* __restrict__ Bgh, const __nv_bfloat16* __restrict__ Bgl,
    const float* __restrict__ bias,
    float* __restrict__ Cf, __nv_bfloat16* __restrict__ Ch, __nv_bfloat16* __restrict__ Cl,
    int N, int bx, int by, char* sm)
{
    const int tid  = threadIdx.x;
    const int wid  = tid >> 5;
    const int lane = tid & 31;
    const int gid  = lane >> 2;
    const int tig  = lane & 3;
    const int wm   = wid & 1;     // 2 warps along M
    const int wn   = wid >> 1;    // 4 warps along N
    const uint32_t smb = (uint32_t)__cvta_generic_to_shared(sm);

    // staging mapping: thread -> (row r, 16B half hk)
    const int r  = tid >> 1;
    const int hk = tid & 1;
    const __nv_bfloat16* a_h = Agh + (size_t)(by * 128 + r) * D_MODEL + hk * 8;
    const __nv_bfloat16* a_l = Agl + (size_t)(by * 128 + r) * D_MODEL + hk * 8;
    const __nv_bfloat16* b_h = Bgh + (size_t)(bx * 128 + r) * D_MODEL + hk * 8;
    const __nv_bfloat16* b_l = Bgl + (size_t)(bx * 128 + r) * D_MODEL + hk * 8;
    const uint32_t dst0 = smb + r * (GSTR * 2) + hk * 16;

    // ldmatrix lane patterns (R9-verified)
    const int l7    = lane & 7;
    const int a_row = l7 + ((lane >> 3) & 1) * 8;
    const int a_col = (lane >> 4) * 8;
    const int b_row = l7 + (lane >> 4) * 8;
    const int b_col = ((lane >> 3) & 1) * 8;

    uint32_t shAh[2], shAl[2], shBh[2], shBl[2];
#pragma unroll
    for (int bu = 0; bu < 2; bu++) {
        const uint32_t base = smb + bu * GBUF;
        shAh[bu] = base +            ((wm * 64 + a_row) * GSTR + a_col) * 2;
        shAl[bu] = base + GARR +     ((wm * 64 + a_row) * GSTR + a_col) * 2;
        shBh[bu] = base + 2 * GARR + ((wn * 32 + b_row) * GSTR + b_col) * 2;
        shBl[bu] = base + 3 * GARR + ((wn * 32 + b_row) * GSTR + b_col) * 2;
    }

    float acc[4][4][4];
#pragma unroll
    for (int i = 0; i < 4; i++)
#pragma unroll
        for (int j = 0; j < 4; j++)
#pragma unroll
            for (int rr = 0; rr < 4; rr++) acc[i][j][rr] = 0.f;

    // prologue: stage tile 0 into buffer 0
    {
        cp16(dst0,            a_h);
        cp16(dst0 + GARR,     a_l);
        cp16(dst0 + 2 * GARR, b_h);
        cp16(dst0 + 3 * GARR, b_l);
        cp_commit();
    }

    const int nk = D_MODEL / GBK;   // 64
    for (int t = 0; t < nk; t++) {
        const int bu = t & 1;
        if (t + 1 < nk) {
            const uint32_t d = dst0 + ((t + 1) & 1) * GBUF;
            const int ko = (t + 1) * GBK;
            cp16(d,            a_h + ko);
            cp16(d + GARR,     a_l + ko);
            cp16(d + 2 * GARR, b_h + ko);
            cp16(d + 3 * GARR, b_l + ko);
            cp_commit();
            cp_wait1();
        } else {
            cp_wait0();
        }
        __syncthreads();

        // B fragments: 2 LDSM.x4 per precision
        unsigned bh[4][2], bl[4][2];
#pragma unroll
        for (int jp = 0; jp < 2; jp++) {
            const unsigned off = (unsigned)(jp * 16 * GSTR * 2);
            unsigned rr[4];
            ldsm_x4(rr, shBh[bu] + off);
            bh[2*jp][0] = rr[0]; bh[2*jp][1] = rr[1];
            bh[2*jp+1][0] = rr[2]; bh[2*jp+1][1] = rr[3];
            ldsm_x4(rr, shBl[bu] + off);
            bl[2*jp][0] = rr[0]; bl[2*jp][1] = rr[1];
            bl[2*jp+1][0] = rr[2]; bl[2*jp+1][1] = rr[3];
        }
        // A fragments per 16-row block, interleaved with mma
#pragma unroll
        for (int i = 0; i < 4; i++) {
            const unsigned off = (unsigned)(i * 16 * GSTR * 2);
            unsigned ah[4], al[4];
            ldsm_x4(ah, shAh[bu] + off);
            ldsm_x4(al, shAl[bu] + off);
#pragma unroll
            for (int j = 0; j < 4; j++) {
                mma_bf16(acc[i][j], ah, bh[j]);
                mma_bf16(acc[i][j], ah, bl[j]);
                mma_bf16(acc[i][j], al, bh[j]);
            }
        }
        __syncthreads();
    }

    // epilogue: bias + store (fp32 or bf16 hi/lo)
#pragma unroll
    for (int i = 0; i < 4; i++) {
        const int row = by * 128 + wm * 64 + i * 16 + gid;
#pragma unroll
        for (int j = 0; j < 4; j++) {
            const int col = bx * 128 + wn * 32 + j * 8 + tig * 2;
            const float b0 = bias[col], b1 = bias[col + 1];
            const float c0 = acc[i][j][0] + b0, c1 = acc[i][j][1] + b1;
            const float c2 = acc[i][j][2] + b0, c3 = acc[i][j][3] + b1;
            if (BF16OUT) {
                unsigned hh, ll;
                split2(c0, c1, hh, ll);
                *(unsigned*)&Ch[(size_t)row * N + col] = hh;
                *(unsigned*)&Cl[(size_t)row * N + col] = ll;
                split2(c2, c3, hh, ll);
                *(unsigned*)&Ch[(size_t)(row + 8) * N + col] = hh;
                *(unsigned*)&Cl[(size_t)(row + 8) * N + col] = ll;
            } else {
                *(float2*)&Cf[(size_t)row * N + col]       = make_float2(c0, c1);
                *(float2*)&Cf[(size_t)(row + 8) * N + col] = make_float2(c2, c3);
            }
        }
    }
}

// fused Q+K+V projections: grid.x 0..7 -> Q tiles; 8..9 -> K; 10..11 -> V
__global__ __launch_bounds__(256) void gemm_qkv(
    const float* __restrict__ bq, const float* __restrict__ bk, const float* __restrict__ bv)
{
    extern __shared__ char sm[];
    const int bx = blockIdx.x;
    if (bx < 8)
        gemm_body<true>(g_xh, g_xl, g_wqt_h, g_wqt_l, bq, nullptr, g_qh, g_ql,
                        D_MODEL, bx, blockIdx.y, sm);
    else if (bx < 10)
        gemm_body<true>(g_xh, g_xl, g_wkt_h, g_wkt_l, bk, nullptr, g_kh, g_kl,
                        KVD, bx - 8, blockIdx.y, sm);
    else
        gemm_body<true>(g_xh, g_xl, g_wvt_h, g_wvt_l, bv, nullptr, g_vh, g_vl,
                        KVD, bx - 10, blockIdx.y, sm);
}

// out projection: fp32 output with bias
__global__ __launch_bounds__(256) void gemm_out(
    const float* __restrict__ bo, float* __restrict__ out)
{
    extern __shared__ char sm[];
    gemm_body<false>(g_ah, g_al, g_wot_h, g_wot_l, bo, out, nullptr, nullptr,
                     D_MODEL, blockIdx.x, blockIdx.y, sm);
}

// ================= tensor-core flash attention (bf16 inputs) =================
#define ASTR 72

__global__ __launch_bounds__(256) void attn_tc()
{
    __shared__ __nv_bfloat16 smKh[64 * ASTR];
    __shared__ __nv_bfloat16 smKl[64 * ASTR];
    __shared__ __nv_bfloat16 smVh[64 * ASTR];   // transposed [d][key]
    __shared__ __nv_bfloat16 smVl[64 * ASTR];

    const int h   = blockIdx.y;
    const int qb  = blockIdx.x * 128;
    const int tid = threadIdx.x;
    const int wid = tid >> 5;
    const int lane = tid & 31;
    const int gid = lane >> 2;
    const int tig = lane & 3;
    const int qw0 = wid * 16;
    const int kvh = h >> 2;
    const float slope2 = exp2f(-0.5f * (float)(h + 1)) * 1.442695041f;
    const float qscale = 0.125f * 1.442695041f;

    const int l7    = lane & 7;
    const int b_row = l7 + (lane >> 4) * 8;
    const int b_col = ((lane >> 3) & 1) * 8;
    const unsigned bOff = (unsigned)((b_row * ASTR + b_col) * 2);
    const unsigned shKhB = (unsigned)__cvta_generic_to_shared(smKh) + bOff;
    const unsigned shKlB = (unsigned)__cvta_generic_to_shared(smKl) + bOff;
    const unsigned shVhB = (unsigned)__cvta_generic_to_shared(smVh) + bOff;
    const unsigned shVlB = (unsigned)__cvta_generic_to_shared(smVl) + bOff;

    // stage Q (128x64 bf16 hi/lo) into K/V smem space temporarily
    {
        __nv_bfloat16* Qh = smKh;
        __nv_bfloat16* Ql = smVh;
        for (int u = tid; u < 128 * 8; u += 256) {
            const int rr = u >> 3;
            const int d8 = (u & 7) << 3;
            const size_t gi = (size_t)(qb + rr) * D_MODEL + h * HD + d8;
            *(uint4*)&Qh[rr * ASTR + d8] = *(const uint4*)&g_qh[gi];
            *(uint4*)&Ql[rr * ASTR + d8] = *(const uint4*)&g_ql[gi];
        }
        __syncthreads();
    }

    unsigned qh[4][4], ql[4][4];
    {
        const __nv_bfloat16* Qh = smKh;
        const __nv_bfloat16* Ql = smVh;
#pragma unroll
        for (int t = 0; t < 4; t++) {
            const int base = (qw0 + gid) * ASTR + 16 * t + 2 * tig;
            qh[t][0] = *(const unsigned*)&Qh[base];
            qh[t][1] = *(const unsigned*)&Qh[base + 8 * ASTR];
            qh[t][2] = *(const unsigned*)&Qh[base + 8];
            qh[t][3] = *(const unsigned*)&Qh[base + 8 * ASTR + 8];
            ql[t][0] = *(const unsigned*)&Ql[base];
            ql[t][1] = *(const unsigned*)&Ql[base + 8 * ASTR];
            ql[t][2] = *(const unsigned*)&Ql[base + 8];
            ql[t][3] = *(const unsigned*)&Ql[base + 8 * ASTR + 8];
        }
        __syncthreads();
    }

    float o[8][4];
#pragma unroll
    for (int j = 0; j < 8; j++)
#pragma unroll
        for (int r = 0; r < 4; r++) o[j][r] = 0.f;
    float lsum0 = 0.f, lsum1 = 0.f;

    const int qi0     = qb + qw0 + gid;
    const int q_first = qb + qw0;
    const int q_last  = q_first + 15;

    int kb0 = qb - WINDOW;
    if (kb0 < 0) kb0 = 0;
    const int kbend = qb + 128;

    for (int kb = kb0; kb < kbend; kb += 64) {
        // K tile [key][d]: straight bf16 copies
        for (int u = tid; u < 64 * 8; u += 256) {
            const int rr = u >> 3;
            const int d8 = (u & 7) << 3;
            const size_t gi = (size_t)(kb + rr) * KVD + kvh * HD + d8;
            *(uint4*)&smKh[rr * ASTR + d8] = *(const uint4*)&g_kh[gi];
            *(uint4*)&smKl[rr * ASTR + d8] = *(const uint4*)&g_kl[gi];
        }
        // V tile transposed [d][key]: pack 2 keys per u32
        for (int u = tid; u < 2048; u += 256) {
            const int d  = u & 63;
            const int kp = u >> 6;
            const size_t gi0 = (size_t)(kb + 2 * kp) * KVD + kvh * HD + d;
            const size_t gi1 = gi0 + KVD;
            unsigned a0 = *(const unsigned short*)&g_vh[gi0];
            unsigned b0 = *(const unsigned short*)&g_vh[gi1];
            *(unsigned*)&smVh[d * ASTR + 2 * kp] = a0 | (b0 << 16);
            unsigned a1 = *(const unsigned short*)&g_vl[gi0];
            unsigned b1 = *(const unsigned short*)&g_vl[gi1];
            *(unsigned*)&smVl[d * ASTR + 2 * kp] = a1 | (b1 << 16);
        }
        __syncthreads();

        const bool active = !(kb > q_last || kb + 63 < q_first - (WINDOW - 1));
        if (active) {
            unsigned ph[8][2], pl[8][2];
            const int dbase = qi0 - kb;
#pragma unroll
            for (int jp = 0; jp < 4; jp++) {
                unsigned kh[4][4], kl[4][4];
#pragma unroll
                for (int t = 0; t < 4; t++) {
                    const unsigned off = (unsigned)((16 * jp * ASTR + 16 * t) * 2);
                    ldsm_x4(kh[t], shKhB + off);
                    ldsm_x4(kl[t], shKlB + off);
                }
                float s0[4] = {0.f, 0.f, 0.f, 0.f};
                float s1[4] = {0.f, 0.f, 0.f, 0.f};
#pragma unroll
                for (int t = 0; t < 4; t++) {
                    unsigned bh0[2] = { kh[t][0], kh[t][1] };
                    unsigned bl0[2] = { kl[t][0], kl[t][1] };
                    unsigned bh1[2] = { kh[t][2], kh[t][3] };
                    unsigned bl1[2] = { kl[t][2], kl[t][3] };
                    mma_bf16(s0, qh[t], bh0);
                    mma_bf16(s0, qh[t], bl0);
                    mma_bf16(s0, ql[t], bh0);
                    mma_bf16(s1, qh[t], bh1);
                    mma_bf16(s1, qh[t], bl1);
                    mma_bf16(s1, ql[t], bh1);
                }
                // scale applied post-mma (Q stored unscaled now)
                {
                    const int d00 = dbase - 16 * jp - 2 * tig;
                    const int d01 = d00 - 1, d10 = d00 + 8, d11 = d00 + 7;
                    float p00 = ((unsigned)d00 < WINDOW) ? ex2(fmaf(-slope2, (float)d00, s0[0] * qscale)) : 0.f;
                    float p01 = ((unsigned)d01 < WINDOW) ? ex2(fmaf(-slope2, (float)d01, s0[1] * qscale)) : 0.f;
                    float p10 = ((unsigned)d10 < WINDOW) ? ex2(fmaf(-slope2, (float)d10, s0[2] * qscale)) : 0.f;
                    float p11 = ((unsigned)d11 < WINDOW) ? ex2(fmaf(-slope2, (float)d11, s0[3] * qscale)) : 0.f;
                    lsum0 += p00 + p01;
                    lsum1 += p10 + p11;
                    split2(p00, p01, ph[2*jp][0], pl[2*jp][0]);
                    split2(p10, p11, ph[2*jp][1], pl[2*jp][1]);
                }
                {
                    const int d00 = dbase - 16 * jp - 8 - 2 * tig;
                    const int d01 = d00 - 1, d10 = d00 + 8, d11 = d00 + 7;
                    float p00 = ((unsigned)d00 < WINDOW) ? ex2(fmaf(-slope2, (float)d00, s1[0] * qscale)) : 0.f;
                    float p01 = ((unsigned)d01 < WINDOW) ? ex2(fmaf(-slope2, (float)d01, s1[1] * qscale)) : 0.f;
                    float p10 = ((unsigned)d10 < WINDOW) ? ex2(fmaf(-slope2, (float)d10, s1[2] * qscale)) : 0.f;
                    float p11 = ((unsigned)d11 < WINDOW) ? ex2(fmaf(-slope2, (float)d11, s1[3] * qscale)) : 0.f;
                    lsum0 += p00 + p01;
                    lsum1 += p10 + p11;
                    split2(p00, p01, ph[2*jp+1][0], pl[2*jp+1][0]);
                    split2(p10, p11, ph[2*jp+1][1], pl[2*jp+1][1]);
                }
            }

            // O += P V
#pragma unroll
            for (int t = 0; t < 4; t++) {
                unsigned ah[4] = { ph[2*t][0], ph[2*t][1], ph[2*t+1][0], ph[2*t+1][1] };
                unsigned al[4] = { pl[2*t][0], pl[2*t][1], pl[2*t+1][0], pl[2*t+1][1] };
#pragma unroll
                for (int jdp = 0; jdp < 4; jdp++) {
                    const unsigned off = (unsigned)((16 * jdp * ASTR + 16 * t) * 2);
                    unsigned vh[4], vl[4];
                    ldsm_x4(vh, shVhB + off);
                    ldsm_x4(vl, shVlB + off);
                    unsigned bh0[2] = { vh[0], vh[1] };
                    unsigned bl0[2] = { vl[0], vl[1] };
                    unsigned bh1[2] = { vh[2], vh[3] };
                    unsigned bl1[2] = { vl[2], vl[3] };
                    mma_bf16(o[2*jdp],   ah, bh0);
                    mma_bf16(o[2*jdp],   ah, bl0);
                    mma_bf16(o[2*jdp],   al, bh0);
                    mma_bf16(o[2*jdp+1], ah, bh1);
                    mma_bf16(o[2*jdp+1], ah, bl1);
                    mma_bf16(o[2*jdp+1], al, bh1);
                }
            }
        }
        __syncthreads();
    }

    lsum0 += __shfl_xor_sync(0xffffffffu, lsum0, 1);
    lsum0 += __shfl_xor_sync(0xffffffffu, lsum0, 2);
    lsum1 += __shfl_xor_sync(0xffffffffu, lsum1, 1);
    lsum1 += __shfl_xor_sync(0xffffffffu, lsum1, 2);
    const float inv0 = 1.f / lsum0;
    const float inv1 = 1.f / lsum1;

    const int row0 = qi0;
#pragma unroll
    for (int jd = 0; jd < 8; jd++) {
        const int col = h * HD + 8 * jd + 2 * tig;
        const float c0 = o[jd][0] * inv0, c1 = o[jd][1] * inv0;
        const float c2 = o[jd][2] * inv1, c3 = o[jd][3] * inv1;
        unsigned hh, ll;
        split2(c0, c1, hh, ll);
        *(unsigned*)&g_ah[(size_t)row0 * D_MODEL + col] = hh;
        *(unsigned*)&g_al[(size_t)row0 * D_MODEL + col] = ll;
        split2(c2, c3, hh, ll);
        *(unsigned*)&g_ah[(size_t)(row0 + 8) * D_MODEL + col] = hh;
        *(unsigned*)&g_al[(size_t)(row0 + 8) * D_MODEL + col] = ll;
    }
}

// ---------------- launch ----------------
extern "C" void kernel_launch(void* const* d_in, const int* in_sizes, int n_in,
                              void* d_out, int out_size)
{
    const float* x  = (const float*)d_in[0];
    const float* Wq = (const float*)d_in[1];
    const float* bq = (const float*)d_in[2];
    const float* Wk = (const float*)d_in[3];
    const float* bk = (const float*)d_in[4];
    const float* Wv = (const float*)d_in[5];
    const float* bv = (const float*)d_in[6];
    const float* Wo = (const float*)d_in[7];
    const float* bo = (const float*)d_in[8];
    float* out = (float*)d_out;

    // one-time conversions (recomputed every call: deterministic)
    conv_x<<<T_SEQ * D_MODEL / (256 * 8), 256>>>(x);
    conv_wt<<<dim3(16, 16, 4), 256>>>(Wq, Wo, Wk, Wv);

    // fused Q+K+V projections: grid (12, 32)
    dim3 gQkv(12, T_SEQ / 128);
    gemm_qkv<<<gQkv, 256, GSM_TOTAL>>>(bq, bk, bv);

    // attention: grid (32, 16)
    dim3 gAttn(T_SEQ / 128, NHEADS);
    attn_tc<<<gAttn, 256>>>();

    // out projection: grid (8, 32)
    dim3 gOut(D_MODEL / 128, T_SEQ / 128);
    gemm_out<<<gOut, 256, GSM_TOTAL>>>(bo, out);
}